// round 15
// baseline (speedup 1.0000x reference)
#include <cuda_runtime.h>
#include <math.h>
#include <stdint.h>

#define H      512
#define IN_DIM 256
#define TSEQ   4096
#define NOUT   5
#define GC     256          // chain grid size (co-residency verified)

// ---------------- static device scratch ------------------------------------
__device__ __align__(16) float g_V1[128 * H];
__device__ __align__(16) float g_V2[ 64 * H];
__device__ __align__(16) float g_V3[ 32 * H];
__device__ __align__(16) float g_V4[ 32 * H];   // 16 valid + 16 zero pad
__device__ __align__(16) float g_V5[ 16 * H];   // 8 valid + 8 zero
__device__ __align__(16) float g_P[5][H * H];   // Wh^2,4,8,16,32
__device__ __align__(16) float g_w[2][H];
__device__ unsigned g_arr[GC];
__device__ unsigned g_rel;
__device__ unsigned g_xdone;

// ---------------- tf32 helpers ----------------------------------------------
__device__ __forceinline__ uint32_t tf32r(float x) {
    uint32_t y;
    asm("cvt.rna.tf32.f32 %0, %1;" : "=r"(y) : "f"(x));
    return y;
}
__device__ __forceinline__ void mma_tf32(float* c, const uint32_t* a, const uint32_t* b) {
    asm volatile("mma.sync.aligned.m16n8k8.row.col.f32.tf32.tf32.f32 "
        "{%0,%1,%2,%3}, {%4,%5,%6,%7}, {%8,%9}, {%0,%1,%2,%3};"
        : "+f"(c[0]), "+f"(c[1]), "+f"(c[2]), "+f"(c[3])
        : "r"(a[0]), "r"(a[1]), "r"(a[2]), "r"(a[3]), "r"(b[0]), "r"(b[1]));
}

// ---------------- zeroAll: P2..P32, V2..V5, sync state -----------------------
__global__ void zeroAll_kernel() {
    int t = blockIdx.x * blockDim.x + threadIdx.x;   // 0..346111
    float4 z = make_float4(0.f, 0.f, 0.f, 0.f);
    const int nP = 5 * H * H / 4;                    // 327680
    if (t < nP) ((float4*)g_P)[t] = z;
    else {
        int u = t - nP;
        if      (u <  8192) ((float4*)g_V2)[u] = z;
        else if (u < 12288) ((float4*)g_V3)[u - 8192] = z;
        else if (u < 16384) ((float4*)g_V4)[u - 12288] = z;
        else if (u < 18432) ((float4*)g_V5)[u - 16384] = z;
    }
    if (t < GC) g_arr[t] = 0u;
    if (t == 0) { g_rel = 0u; g_xdone = 0u; }
}

// ---------------- xfuse: gather + xproj + tree level 1 (s1 node) -------------
// CTA r (128): V1[r] = y_{2r} + Wh*y_{2r+1}. Signals g_xdone on completion.
__global__ void __launch_bounds__(256, 1)
xfuse_kernel(const int* __restrict__ tokens, const float* __restrict__ emb,
             const float* __restrict__ Wi, const float* __restrict__ bi) {
    __shared__ float xe[IN_DIM], xo[IN_DIM], ve[H], vo[H];
    __shared__ int stok[2];
    int tid = threadIdx.x, w = tid >> 5, lane = tid & 31;
    int r = blockIdx.x;
    if (tid < 2) stok[tid] = tokens[TSEQ - 1 - 2 * r - tid];
    __syncthreads();
    {
        const float* ee = emb + (size_t)stok[0] * IN_DIM;
        const float* eo = emb + (size_t)stok[1] * IN_DIM;
        xe[tid] = ee[tid];
        xo[tid] = eo[tid];
    }
    __syncthreads();
    for (int i = w; i < H; i += 8) {
        const float* wr = Wi + (size_t)i * 768 + lane * 8;
        float4 a0 = *(const float4*)wr;
        float4 a1 = *(const float4*)(wr + 4);
        float4 xe0 = *(const float4*)&xe[lane * 8];
        float4 xe1 = *(const float4*)&xe[lane * 8 + 4];
        float4 xo0 = *(const float4*)&xo[lane * 8];
        float4 xo1 = *(const float4*)&xo[lane * 8 + 4];
        float ae = a0.x*xe0.x + a0.y*xe0.y + a0.z*xe0.z + a0.w*xe0.w
                 + a1.x*xe1.x + a1.y*xe1.y + a1.z*xe1.z + a1.w*xe1.w;
        float ao = a0.x*xo0.x + a0.y*xo0.y + a0.z*xo0.z + a0.w*xo0.w
                 + a1.x*xo1.x + a1.y*xo1.y + a1.z*xo1.z + a1.w*xo1.w;
#pragma unroll
        for (int s = 16; s > 0; s >>= 1) {
            ae += __shfl_xor_sync(0xffffffffu, ae, s);
            ao += __shfl_xor_sync(0xffffffffu, ao, s);
        }
        if (lane == 0) {
            float b = bi[i];
            ve[i] = ae + b;
            vo[i] = ao + b;
        }
    }
    __syncthreads();
    for (int i = w; i < H; i += 8) {
        const float* hr = Wi + (size_t)i * 768 + IN_DIM;
        float acc = 0.f;
#pragma unroll
        for (int jj = 0; jj < 4; jj++) {
            float4 hv = *(const float4*)(hr + jj * 128 + lane * 4);
            float4 vv = *(const float4*)&vo[jj * 128 + lane * 4];
            acc += hv.x*vv.x + hv.y*vv.y + hv.z*vv.z + hv.w*vv.w;
        }
#pragma unroll
        for (int s = 16; s > 0; s >>= 1) acc += __shfl_xor_sync(0xffffffffu, acc, s);
        if (lane == 0) g_V1[(size_t)r * H + i] = acc + ve[i];
    }
    __syncthreads();
    if (tid == 0) { __threadfence(); atomicAdd(&g_xdone, 1u); }
}

// ---------------- sqmm task: 64x64 tile, K-chunk 128, 3xTF32 MMA ------------
// smem: AH[64*36], AL, BH[32*68], BL = 8960 floats = 35840 B.
#define SQ_SMEM (8960 * 4)
__device__ __forceinline__ void sqmm_task(const float* A, int lda, float* C,
                                          int m0, int n0, int kbeg, float* sm) {
    float* AH = sm;
    float* AL = sm + 2304;
    float* BH = sm + 4608;
    float* BL = sm + 6784;
    int tid = threadIdx.x, wid = tid >> 5, lane = tid & 31;
    int g = lane >> 2, t4 = lane & 3;
    int wr = (wid >> 1) * 32, wc = (wid & 1) * 32;

    float c_[2][4][4];
#pragma unroll
    for (int mt = 0; mt < 2; mt++)
#pragma unroll
        for (int nt = 0; nt < 4; nt++)
#pragma unroll
            for (int q = 0; q < 4; q++) c_[mt][nt][q] = 0.f;

#pragma unroll
    for (int kt = 0; kt < 4; kt++) {
        int kb = kbeg + kt * 32;
        __syncthreads();
#pragma unroll
        for (int u0 = 0; u0 < 4; u0++) {            // A 64x32
            int u = u0 * 128 + tid;
            int row = u >> 3, col = (u & 7) * 4;
            float4 v = *(const float4*)&A[(size_t)(m0 + row) * lda + kb + col];
            uint32_t h0 = tf32r(v.x), h1 = tf32r(v.y), h2 = tf32r(v.z), h3 = tf32r(v.w);
            uint4 hv; hv.x = h0; hv.y = h1; hv.z = h2; hv.w = h3;
            uint4 lv;
            lv.x = tf32r(v.x - __uint_as_float(h0));
            lv.y = tf32r(v.y - __uint_as_float(h1));
            lv.z = tf32r(v.z - __uint_as_float(h2));
            lv.w = tf32r(v.w - __uint_as_float(h3));
            *(uint4*)&AH[row * 36 + col] = hv;
            *(uint4*)&AL[row * 36 + col] = lv;
        }
#pragma unroll
        for (int u0 = 0; u0 < 4; u0++) {            // B 32x64
            int u = u0 * 128 + tid;
            int row = u >> 4, col = (u & 15) * 4;
            float4 v = *(const float4*)&A[(size_t)(kb + row) * lda + n0 + col];
            uint32_t h0 = tf32r(v.x), h1 = tf32r(v.y), h2 = tf32r(v.z), h3 = tf32r(v.w);
            uint4 hv; hv.x = h0; hv.y = h1; hv.z = h2; hv.w = h3;
            uint4 lv;
            lv.x = tf32r(v.x - __uint_as_float(h0));
            lv.y = tf32r(v.y - __uint_as_float(h1));
            lv.z = tf32r(v.z - __uint_as_float(h2));
            lv.w = tf32r(v.w - __uint_as_float(h3));
            *(uint4*)&BH[row * 68 + col] = hv;
            *(uint4*)&BL[row * 68 + col] = lv;
        }
        __syncthreads();
#pragma unroll
        for (int kk = 0; kk < 32; kk += 8) {
            uint32_t ah[2][4], al[2][4], bh[4][2], bl[4][2];
#pragma unroll
            for (int mt = 0; mt < 2; mt++) {
                int r = wr + mt * 16 + g;
                const float* ph = &AH[r * 36 + kk + t4];
                const float* pl = &AL[r * 36 + kk + t4];
                ah[mt][0] = __float_as_uint(ph[0]);
                ah[mt][1] = __float_as_uint(ph[8 * 36]);
                ah[mt][2] = __float_as_uint(ph[4]);
                ah[mt][3] = __float_as_uint(ph[8 * 36 + 4]);
                al[mt][0] = __float_as_uint(pl[0]);
                al[mt][1] = __float_as_uint(pl[8 * 36]);
                al[mt][2] = __float_as_uint(pl[4]);
                al[mt][3] = __float_as_uint(pl[8 * 36 + 4]);
            }
#pragma unroll
            for (int nt = 0; nt < 4; nt++) {
                int cc = wc + nt * 8 + g;
                bh[nt][0] = __float_as_uint(BH[(kk + t4) * 68 + cc]);
                bh[nt][1] = __float_as_uint(BH[(kk + t4 + 4) * 68 + cc]);
                bl[nt][0] = __float_as_uint(BL[(kk + t4) * 68 + cc]);
                bl[nt][1] = __float_as_uint(BL[(kk + t4 + 4) * 68 + cc]);
            }
#pragma unroll
            for (int mt = 0; mt < 2; mt++)
#pragma unroll
                for (int nt = 0; nt < 4; nt++) {
                    mma_tf32(c_[mt][nt], ah[mt], bh[nt]);
                    mma_tf32(c_[mt][nt], ah[mt], bl[nt]);
                    mma_tf32(c_[mt][nt], al[mt], bh[nt]);
                }
        }
    }
#pragma unroll
    for (int mt = 0; mt < 2; mt++)
#pragma unroll
        for (int nt = 0; nt < 4; nt++) {
            int r = m0 + wr + mt * 16 + g;
            int cc = n0 + wc + nt * 8 + t4 * 2;
            atomicAdd(&C[(size_t)r * H + cc],           c_[mt][nt][0]);
            atomicAdd(&C[(size_t)r * H + cc + 1],       c_[mt][nt][1]);
            atomicAdd(&C[(size_t)(r + 8) * H + cc],     c_[mt][nt][2]);
            atomicAdd(&C[(size_t)(r + 8) * H + cc + 1], c_[mt][nt][3]);
        }
}

// ---------------- tree task: C[16 x 64] += A[16 x K]*P^T-style ---------------
// C[p][j0+j] += sum_k A[(r0+p)][k] * P[(j0+j)][k]  (+D once at kbeg==0)
__device__ void tree_task(const float* A, int lda, const float* P,
                          const float* D, int ldd, float* C,
                          int r0, int j0, int kbeg, int nblk, float* sm) {
    float* As = sm;              // 16*36
    float* Bs = sm + 16 * 36;    // 32*68
    int tid = threadIdx.x;
    int r = tid >> 3, c8 = (tid & 7) * 8;
    float acc[8];
#pragma unroll
    for (int q = 0; q < 8; q++) acc[q] = 0.f;
    for (int b = 0; b < nblk; b++) {
        int kb = kbeg + b * 32;
        __syncthreads();
        {   // A 16x32, one f4 per thread
            int row = tid >> 3, kp = (tid & 7) * 4;
            float4 v = __ldcg((const float4*)&A[(size_t)(r0 + row) * lda + kb + kp]);
            *(float4*)&As[row * 36 + kp] = v;
        }
#pragma unroll
        for (int u0 = 0; u0 < 4; u0++) {   // P rows j0..j0+63, cols kb..kb+31 -> Bs[k][j]
            int u = u0 * 128 + tid;
            int row = u >> 3, kp = (u & 7) * 4;
            float4 v = *(const float4*)&P[(size_t)(j0 + row) * H + kb + kp];
            Bs[(kp + 0) * 68 + row] = v.x;
            Bs[(kp + 1) * 68 + row] = v.y;
            Bs[(kp + 2) * 68 + row] = v.z;
            Bs[(kp + 3) * 68 + row] = v.w;
        }
        __syncthreads();
#pragma unroll
        for (int k = 0; k < 32; k++) {
            float a = As[r * 36 + k];
            float4 b0 = *(const float4*)&Bs[k * 68 + c8];
            float4 b1 = *(const float4*)&Bs[k * 68 + c8 + 4];
            acc[0] += a * b0.x; acc[1] += a * b0.y; acc[2] += a * b0.z; acc[3] += a * b0.w;
            acc[4] += a * b1.x; acc[5] += a * b1.y; acc[6] += a * b1.z; acc[7] += a * b1.w;
        }
    }
    int row = r0 + r;
    bool z0 = (kbeg == 0);
#pragma unroll
    for (int q = 0; q < 8; q++) {
        float v = acc[q];
        int col = j0 + c8 + q;
        if (z0) v += __ldcg(&D[(size_t)row * ldd + col]);
        atomicAdd(&C[(size_t)row * H + col], v);
    }
}

// ---------------- grid barrier (GC CTAs, 128 threads, per-CTA flags) ---------
__device__ __forceinline__ void gridbar(unsigned phase) {
    __threadfence();
    __syncthreads();
    int tid = threadIdx.x;
    if (blockIdx.x == 0) {
        for (int idx = tid; idx < GC; idx += 128)
            if (idx > 0) while (*(volatile unsigned*)&g_arr[idx] < phase) { }
        __syncthreads();
        if (tid == 0) { __threadfence(); *(volatile unsigned*)&g_rel = phase; }
        __syncthreads();
    } else {
        if (tid == 0) {
            *(volatile unsigned*)&g_arr[blockIdx.x] = phase;
            while (*(volatile unsigned*)&g_rel < phase) { }
        }
        __syncthreads();
    }
}

// ---------------- chain: 5 squarings + tree L2..L5 + Horner + readout --------
// MUST launch with GC=256 CTAs x 128 threads, SQ_SMEM dynamic smem.
__global__ void __launch_bounds__(128, 3)
chain_kernel(const float* __restrict__ Wi, const float* __restrict__ Wo,
             const float* __restrict__ bo, float* __restrict__ out) {
    extern __shared__ float sm[];
    const float* Wh = Wi + IN_DIM;
    int cta = blockIdx.x, tid = threadIdx.x;
    int wid = tid >> 5, lane = tid & 31;
    // sqmm tile mapping: 8x8x4
    int zi = cta & 3, yi = (cta >> 2) & 7, xi = (cta >> 5) & 7;
    int m0 = xi * 64, n0 = yi * 64, kb = zi * 128;
    float* P2  = g_P[0];
    float* P4  = g_P[1];
    float* P8  = g_P[2];
    float* P16 = g_P[3];
    float* P32 = g_P[4];

    // ph1
    sqmm_task(Wh, 768, P2, m0, n0, kb, sm);
    gridbar(1);
    // ph2
    sqmm_task(P2, 512, P4, m0, n0, kb, sm);
    gridbar(2);
    // ph3: sqmm + acquire xfuse + L2
    sqmm_task(P4, 512, P8, m0, n0, kb, sm);
    if (tid == 0) { while (*(volatile unsigned*)&g_xdone < 128u) { } }
    __syncthreads();
    __threadfence();
    tree_task(g_V1 + H, 2 * H, P2, g_V1, 2 * H, g_V2,
              (cta >> 6) * 16, ((cta >> 3) & 7) * 64, (cta & 7) * 64, 2, sm);
    gridbar(3);
    // ph4: sqmm + L3
    sqmm_task(P8, 512, P16, m0, n0, kb, sm);
    tree_task(g_V2 + H, 2 * H, P4, g_V2, 2 * H, g_V3,
              (cta >> 7) * 16, ((cta >> 4) & 7) * 64, (cta & 15) * 32, 1, sm);
    gridbar(4);
    // ph5: sqmm + L4 (128 tasks)
    sqmm_task(P16, 512, P32, m0, n0, kb, sm);
    if (cta < 128)
        tree_task(g_V3 + H, 2 * H, P8, g_V3, 2 * H, g_V4,
                  0, ((cta >> 4) & 7) * 64, (cta & 15) * 32, 1, sm);
    gridbar(5);
    // ph6: L5 (128 tasks)
    if (cta < 128)
        tree_task(g_V4 + H, 2 * H, P16, g_V4, 2 * H, g_V5,
                  0, ((cta >> 4) & 7) * 64, (cta & 15) * 32, 1, sm);
    gridbar(6);

    // Horner: each CTA owns rows cta*2, cta*2+1; cache its 2 P32 rows.
    __syncthreads();
    for (int u = tid; u < 256; u += 128) {
        int rr = u >> 7, c = (u & 127) * 4;
        *(float4*)&sm[rr * H + c] = *(const float4*)&P32[(size_t)(cta * 2 + rr) * H + c];
    }
    __syncthreads();
    for (int t = 0; t < 7; t++) {
        if (wid < 2) {
            int i = cta * 2 + wid;
            const float* src = (t == 0) ? (g_V5 + 7 * H) : g_w[(t - 1) & 1];
            float acc = 0.f;
#pragma unroll
            for (int jj = 0; jj < 4; jj++) {
                float4 pv = *(const float4*)&sm[wid * H + jj * 128 + lane * 4];
                float4 vv = __ldcg((const float4*)(src + jj * 128 + lane * 4));
                acc += pv.x*vv.x + pv.y*vv.y + pv.z*vv.z + pv.w*vv.w;
            }
#pragma unroll
            for (int s = 16; s > 0; s >>= 1) acc += __shfl_xor_sync(0xffffffffu, acc, s);
            if (lane == 0)
                g_w[t & 1][i] = acc + __ldcg(&g_V5[(size_t)(6 - t) * H + i]);
        }
        gridbar(7u + (unsigned)t);
    }

    // readout (CTA 0): h in g_w[0] (t=6)
    if (cta == 0) {
        __shared__ float sl[NOUT];
        *(float4*)&sm[tid * 4] = __ldcg((const float4*)&g_w[0][tid * 4]);
        __syncthreads();
        for (int o = wid; o < NOUT; o += 4) {
            const float* wr = Wo + (size_t)o * H;
            float acc = 0.f;
#pragma unroll
            for (int jj = 0; jj < 4; jj++) {
                float4 pv = *(const float4*)(wr + jj * 128 + lane * 4);
                float4 vv = *(const float4*)&sm[jj * 128 + lane * 4];
                acc += pv.x*vv.x + pv.y*vv.y + pv.z*vv.z + pv.w*vv.w;
            }
#pragma unroll
            for (int s = 16; s > 0; s >>= 1) acc += __shfl_xor_sync(0xffffffffu, acc, s);
            if (lane == 0) sl[o] = acc + bo[o];
        }
        __syncthreads();
        if (tid == 0) {
            float mx = sl[0];
            for (int o = 1; o < NOUT; o++) mx = fmaxf(mx, sl[o]);
            float se = 0.f;
            for (int o = 0; o < NOUT; o++) se += expf(sl[o] - mx);
            float lse = mx + logf(se);
            for (int o = 0; o < NOUT; o++) out[o] = sl[o] - lse;
        }
    }
}

// ---------------- launch (3 nodes; s1 joined back into stream 0) -------------
extern "C" void kernel_launch(void* const* d_in, const int* in_sizes, int n_in,
                              void* d_out, int out_size) {
    const int*   tokens = (const int*)d_in[0];
    const float* emb    = (const float*)d_in[1];
    const float* Wi     = (const float*)d_in[2];
    const float* bi     = (const float*)d_in[3];
    const float* Wo     = (const float*)d_in[4];
    const float* bo     = (const float*)d_in[5];
    float* out = (float*)d_out;

    static cudaStream_t s1 = nullptr;
    static cudaEvent_t eZ, eXF;
    if (!s1) {
        cudaStreamCreateWithFlags(&s1, cudaStreamNonBlocking);
        cudaEventCreateWithFlags(&eZ,  cudaEventDisableTiming);
        cudaEventCreateWithFlags(&eXF, cudaEventDisableTiming);
        cudaFuncSetAttribute(chain_kernel,
                             cudaFuncAttributeMaxDynamicSharedMemorySize, SQ_SMEM);
    }

    // zeroAll resets sync state; xfuse must start after it (eZ fork).
    zeroAll_kernel<<<1352, 256>>>();
    cudaEventRecord(eZ, 0);
    cudaStreamWaitEvent(s1, eZ, 0);
    xfuse_kernel<<<128, 256, 0, s1>>>(tokens, emb, Wi, bi);
    cudaEventRecord(eXF, s1);
    chain_kernel<<<GC, 128, SQ_SMEM>>>(Wi, Wo, bo, out);
    // join s1 into the capture-origin stream (graph requires all forks joined);
    // placed AFTER chain so chain still overlaps xfuse (data sync via g_xdone).
    cudaStreamWaitEvent(0, eXF, 0);
}

// round 16
// speedup vs baseline: 1.4414x; 1.4414x over previous
#include <cuda_runtime.h>
#include <math.h>
#include <stdint.h>

#define H      512
#define IN_DIM 256
#define TSEQ   4096
#define NOUT   5
#define HC     64           // horner grid (64 CTAs x 8 warps = 512 rows)

// ---------------- static device scratch ------------------------------------
__device__ __align__(16) float g_V1[128 * H];   // level-1 (xfuse)
__device__ __align__(16) float g_V2[ 64 * H];
__device__ __align__(16) float g_V3[ 32 * H];
__device__ __align__(16) float g_V4[ 32 * H];   // 16 valid + 16 zero pad
__device__ __align__(16) float g_V5[ 16 * H];   // 8 valid + 8 zero
__device__ __align__(16) float g_P[5][H * H];   // Wh^2,4,8,16,32
__device__ __align__(16) float g_w[2][H];
__device__ unsigned g_arr[HC];
__device__ unsigned g_rel;

// ---------------- tf32 helpers ----------------------------------------------
__device__ __forceinline__ uint32_t tf32r(float x) {
    uint32_t y;
    asm("cvt.rna.tf32.f32 %0, %1;" : "=r"(y) : "f"(x));
    return y;
}
__device__ __forceinline__ void mma_tf32(float* c, const uint32_t* a, const uint32_t* b) {
    asm volatile("mma.sync.aligned.m16n8k8.row.col.f32.tf32.tf32.f32 "
        "{%0,%1,%2,%3}, {%4,%5,%6,%7}, {%8,%9}, {%0,%1,%2,%3};"
        : "+f"(c[0]), "+f"(c[1]), "+f"(c[2]), "+f"(c[3])
        : "r"(a[0]), "r"(a[1]), "r"(a[2]), "r"(a[3]), "r"(b[0]), "r"(b[1]));
}

// ---------------- zeroP2: P2 + barrier state ---------------------------------
__global__ void zeroP2_kernel() {
    int t = blockIdx.x * blockDim.x + threadIdx.x;   // 0..65535
    ((float4*)g_P)[t] = make_float4(0.f, 0.f, 0.f, 0.f);
    if (t < HC) g_arr[t] = 0u;
    if (t == 0) g_rel = 0u;
}

// ---------------- zeroRest: P4..P32 + V2..V5 ---------------------------------
__global__ void zeroRest_kernel() {
    int t = blockIdx.x * blockDim.x + threadIdx.x;
    float4 z = make_float4(0.f, 0.f, 0.f, 0.f);
    const int nP = 4 * H * H / 4;
    if (t < nP) { ((float4*)(g_P[1]))[t] = z; return; }
    int u = t - nP;
    if      (u <  8192) ((float4*)g_V2)[u] = z;
    else if (u < 12288) ((float4*)g_V3)[u - 8192] = z;
    else if (u < 16384) ((float4*)g_V4)[u - 12288] = z;
    else if (u < 18432) ((float4*)g_V5)[u - 16384] = z;
}

// ---------------- xfuse: gather + xproj + tree level 1 ----------------------
// CTA r (128): V1[r] = y_{2r} + Wh*y_{2r+1},  y_k = Wx*emb[tok[T-1-k]] + bi
__global__ void __launch_bounds__(256, 1)
xfuse_kernel(const int* __restrict__ tokens, const float* __restrict__ emb,
             const float* __restrict__ Wi, const float* __restrict__ bi) {
    __shared__ float xe[IN_DIM], xo[IN_DIM], ve[H], vo[H];
    __shared__ int stok[2];
    int tid = threadIdx.x, w = tid >> 5, lane = tid & 31;
    int r = blockIdx.x;
    if (tid < 2) stok[tid] = tokens[TSEQ - 1 - 2 * r - tid];
    __syncthreads();
    {
        const float* ee = emb + (size_t)stok[0] * IN_DIM;
        const float* eo = emb + (size_t)stok[1] * IN_DIM;
        xe[tid] = ee[tid];
        xo[tid] = eo[tid];
    }
    __syncthreads();
    for (int i = w; i < H; i += 8) {
        const float* wr = Wi + (size_t)i * 768 + lane * 8;
        float4 a0 = *(const float4*)wr;
        float4 a1 = *(const float4*)(wr + 4);
        float4 xe0 = *(const float4*)&xe[lane * 8];
        float4 xe1 = *(const float4*)&xe[lane * 8 + 4];
        float4 xo0 = *(const float4*)&xo[lane * 8];
        float4 xo1 = *(const float4*)&xo[lane * 8 + 4];
        float ae = a0.x*xe0.x + a0.y*xe0.y + a0.z*xe0.z + a0.w*xe0.w
                 + a1.x*xe1.x + a1.y*xe1.y + a1.z*xe1.z + a1.w*xe1.w;
        float ao = a0.x*xo0.x + a0.y*xo0.y + a0.z*xo0.z + a0.w*xo0.w
                 + a1.x*xo1.x + a1.y*xo1.y + a1.z*xo1.z + a1.w*xo1.w;
#pragma unroll
        for (int s = 16; s > 0; s >>= 1) {
            ae += __shfl_xor_sync(0xffffffffu, ae, s);
            ao += __shfl_xor_sync(0xffffffffu, ao, s);
        }
        if (lane == 0) {
            float b = bi[i];
            ve[i] = ae + b;
            vo[i] = ao + b;
        }
    }
    __syncthreads();
    for (int i = w; i < H; i += 8) {
        const float* hr = Wi + (size_t)i * 768 + IN_DIM;
        float acc = 0.f;
#pragma unroll
        for (int jj = 0; jj < 4; jj++) {
            float4 hv = *(const float4*)(hr + jj * 128 + lane * 4);
            float4 vv = *(const float4*)&vo[jj * 128 + lane * 4];
            acc += hv.x*vv.x + hv.y*vv.y + hv.z*vv.z + hv.w*vv.w;
        }
#pragma unroll
        for (int s = 16; s > 0; s >>= 1) acc += __shfl_xor_sync(0xffffffffu, acc, s);
        if (lane == 0) g_V1[(size_t)r * H + i] = acc + ve[i];
    }
}

// ---------------- generic NT GEMM (tree levels) ------------------------------
__global__ void gemm_nt(const float* __restrict__ A, int lda,
                        const float* __restrict__ B, int ldb,
                        const float* __restrict__ D, int ldd,
                        const float* __restrict__ bias,
                        float* __restrict__ C, int Ktot) {
    __shared__ float As[16][34];
    __shared__ float Bs[32][68];
    int tid = threadIdx.x;
    int r0 = blockIdx.x * 16;
    int j0 = blockIdx.y * 64;
    int nz = gridDim.z;
    int chunk = Ktot / nz;
    int kbeg = blockIdx.z * chunk;
    int r  = tid >> 4;
    int c4 = tid & 15;
    float acc[4] = {0.f, 0.f, 0.f, 0.f};
    for (int kt = kbeg; kt < kbeg + chunk; kt += 32) {
        {
            int row = tid >> 4, kp = (tid & 15) * 2;
            const float* p = A + (size_t)(r0 + row) * lda + kt + kp;
            float2 v = *(const float2*)p;
            As[row][kp] = v.x; As[row][kp + 1] = v.y;
        }
        {
            int row = tid >> 2, kp = (tid & 3) * 8;
            const float* p = B + (size_t)(j0 + row) * ldb + kt + kp;
            float4 v0 = *(const float4*)p;
            float4 v1 = *(const float4*)(p + 4);
            Bs[kp + 0][row] = v0.x; Bs[kp + 1][row] = v0.y;
            Bs[kp + 2][row] = v0.z; Bs[kp + 3][row] = v0.w;
            Bs[kp + 4][row] = v1.x; Bs[kp + 5][row] = v1.y;
            Bs[kp + 6][row] = v1.z; Bs[kp + 7][row] = v1.w;
        }
        __syncthreads();
#pragma unroll
        for (int k = 0; k < 32; k++) {
            float a = As[r][k];
            float4 b = *(const float4*)&Bs[k][c4 * 4];
            acc[0] += a * b.x; acc[1] += a * b.y;
            acc[2] += a * b.z; acc[3] += a * b.w;
        }
        __syncthreads();
    }
    int row = r0 + r;
    int col = j0 + c4 * 4;
    if (nz == 1) {
        float4 o;
        o.x = acc[0]; o.y = acc[1]; o.z = acc[2]; o.w = acc[3];
        if (D) {
            const float4 d = *(const float4*)&D[(size_t)row * ldd + col];
            o.x += d.x; o.y += d.y; o.z += d.z; o.w += d.w;
        }
        if (bias) {
            const float4 b = *(const float4*)&bias[col];
            o.x += b.x; o.y += b.y; o.z += b.z; o.w += b.w;
        }
        *(float4*)&C[(size_t)row * H + col] = o;
    } else {
        bool z0 = (blockIdx.z == 0);
#pragma unroll
        for (int t = 0; t < 4; t++) {
            float v = acc[t];
            if (z0 && D) v += D[(size_t)row * ldd + col + t];
            atomicAdd(&C[(size_t)row * H + col + t], v);
        }
    }
}

// ---------------- sqmm_mma: C += A*A via 3xTF32 mma.sync --------------------
// 64x64 tile, 128 threads (4 warps of 32x32), split-K=4 (chunk 128),
// grid (8,8,4) = 256 CTAs. hi/lo INTERLEAVED smem: one float2 LDS per
// fragment pair (halves LDS issue). C pre-zeroed (atomicAdd epilogue).
#define A_STR 76     // 64 rows x 76 (2*32 data + pad); 76%32=12 -> CF reads
#define B_STR 136    // 32 rows x 136 (2*64 + pad); CF within half-warp phase
#define SQ_SMEM ((64 * A_STR + 32 * B_STR) * 4)   // 36864 B

__global__ void __launch_bounds__(128, 4)
sqmm_mma(const float* __restrict__ A, int lda, float* __restrict__ C) {
    extern __shared__ float sm[];
    float* AHL = sm;                   // 64 x A_STR, (hi,lo) pairs
    float* BHL = sm + 64 * A_STR;      // 32 x B_STR, (hi,lo) pairs
    int tid = threadIdx.x, wid = tid >> 5, lane = tid & 31;
    int g = lane >> 2, t4 = lane & 3;
    int m0 = blockIdx.x * 64;
    int n0 = blockIdx.y * 64;
    int kbeg = blockIdx.z * 128;
    int wr = (wid >> 1) * 32;    // warp row base (0,32)
    int wc = (wid & 1) * 32;     // warp col base (0,32)

    float c_[2][4][4];
#pragma unroll
    for (int mt = 0; mt < 2; mt++)
#pragma unroll
        for (int nt = 0; nt < 4; nt++)
#pragma unroll
            for (int q = 0; q < 4; q++) c_[mt][nt][q] = 0.f;

#pragma unroll
    for (int kt = 0; kt < 4; kt++) {
        int kb = kbeg + kt * 32;
        __syncthreads();
        // ---- A tile 64x32 -> interleaved hi/lo ----
#pragma unroll
        for (int u0 = 0; u0 < 4; u0++) {
            int u = u0 * 128 + tid;
            int row = u >> 3, col = (u & 7) * 4;
            float4 v = *(const float4*)&A[(size_t)(m0 + row) * lda + kb + col];
            uint32_t h0 = tf32r(v.x), h1 = tf32r(v.y), h2 = tf32r(v.z), h3 = tf32r(v.w);
            float l0 = __uint_as_float(tf32r(v.x - __uint_as_float(h0)));
            float l1 = __uint_as_float(tf32r(v.y - __uint_as_float(h1)));
            float l2 = __uint_as_float(tf32r(v.z - __uint_as_float(h2)));
            float l3 = __uint_as_float(tf32r(v.w - __uint_as_float(h3)));
            float* d = &AHL[row * A_STR + 2 * col];
            float4 s0; s0.x = __uint_as_float(h0); s0.y = l0;
                       s0.z = __uint_as_float(h1); s0.w = l1;
            float4 s1; s1.x = __uint_as_float(h2); s1.y = l2;
                       s1.z = __uint_as_float(h3); s1.w = l3;
            *(float4*)d       = s0;
            *(float4*)(d + 4) = s1;
        }
        // ---- B tile 32x64 (rows kb..kb+31 of A) -> interleaved hi/lo ----
#pragma unroll
        for (int u0 = 0; u0 < 4; u0++) {
            int u = u0 * 128 + tid;
            int row = u >> 4, col = (u & 15) * 4;
            float4 v = *(const float4*)&A[(size_t)(kb + row) * lda + n0 + col];
            uint32_t h0 = tf32r(v.x), h1 = tf32r(v.y), h2 = tf32r(v.z), h3 = tf32r(v.w);
            float l0 = __uint_as_float(tf32r(v.x - __uint_as_float(h0)));
            float l1 = __uint_as_float(tf32r(v.y - __uint_as_float(h1)));
            float l2 = __uint_as_float(tf32r(v.z - __uint_as_float(h2)));
            float l3 = __uint_as_float(tf32r(v.w - __uint_as_float(h3)));
            float* d = &BHL[row * B_STR + 2 * col];
            float4 s0; s0.x = __uint_as_float(h0); s0.y = l0;
                       s0.z = __uint_as_float(h1); s0.w = l1;
            float4 s1; s1.x = __uint_as_float(h2); s1.y = l2;
                       s1.z = __uint_as_float(h3); s1.w = l3;
            *(float4*)d       = s0;
            *(float4*)(d + 4) = s1;
        }
        __syncthreads();
        // ---- 4 k8 steps: float2 fragment loads (hi+lo together) ----
#pragma unroll
        for (int kk = 0; kk < 32; kk += 8) {
            uint32_t ah[2][4], al[2][4], bh[4][2], bl[4][2];
#pragma unroll
            for (int mt = 0; mt < 2; mt++) {
                int base = (wr + mt * 16 + g) * A_STR + 2 * (kk + t4);
                float2 p0 = *(const float2*)&AHL[base];
                float2 p1 = *(const float2*)&AHL[base + 8 * A_STR];
                float2 p2 = *(const float2*)&AHL[base + 8];
                float2 p3 = *(const float2*)&AHL[base + 8 * A_STR + 8];
                ah[mt][0] = __float_as_uint(p0.x); al[mt][0] = __float_as_uint(p0.y);
                ah[mt][1] = __float_as_uint(p1.x); al[mt][1] = __float_as_uint(p1.y);
                ah[mt][2] = __float_as_uint(p2.x); al[mt][2] = __float_as_uint(p2.y);
                ah[mt][3] = __float_as_uint(p3.x); al[mt][3] = __float_as_uint(p3.y);
            }
#pragma unroll
            for (int nt = 0; nt < 4; nt++) {
                int cb = (kk + t4) * B_STR + 2 * (wc + nt * 8 + g);
                float2 q0 = *(const float2*)&BHL[cb];
                float2 q1 = *(const float2*)&BHL[cb + 4 * B_STR];
                bh[nt][0] = __float_as_uint(q0.x); bl[nt][0] = __float_as_uint(q0.y);
                bh[nt][1] = __float_as_uint(q1.x); bl[nt][1] = __float_as_uint(q1.y);
            }
#pragma unroll
            for (int mt = 0; mt < 2; mt++)
#pragma unroll
                for (int nt = 0; nt < 4; nt++) {
                    mma_tf32(c_[mt][nt], ah[mt], bh[nt]);
                    mma_tf32(c_[mt][nt], ah[mt], bl[nt]);
                    mma_tf32(c_[mt][nt], al[mt], bh[nt]);
                }
        }
    }
    // ---- epilogue: atomicAdd into pre-zeroed C ----
#pragma unroll
    for (int mt = 0; mt < 2; mt++)
#pragma unroll
        for (int nt = 0; nt < 4; nt++) {
            int r = m0 + wr + mt * 16 + g;
            int cc = n0 + wc + nt * 8 + t4 * 2;
            atomicAdd(&C[(size_t)r * H + cc],           c_[mt][nt][0]);
            atomicAdd(&C[(size_t)r * H + cc + 1],       c_[mt][nt][1]);
            atomicAdd(&C[(size_t)(r + 8) * H + cc],     c_[mt][nt][2]);
            atomicAdd(&C[(size_t)(r + 8) * H + cc + 1], c_[mt][nt][3]);
        }
}

// ---------------- grid barrier (64 CTAs, per-CTA flags) ----------------------
__device__ __forceinline__ void gridbar(unsigned phase) {
    __threadfence();
    __syncthreads();
    int tid = threadIdx.x;
    if (blockIdx.x == 0) {
        if (tid > 0 && tid < HC) {
            while (*(volatile unsigned*)&g_arr[tid] < phase) { }
        }
        __syncthreads();
        if (tid == 0) {
            __threadfence();
            *(volatile unsigned*)&g_rel = phase;
        }
        __syncthreads();
    } else {
        if (tid == 0) {
            *(volatile unsigned*)&g_arr[blockIdx.x] = phase;
            while (*(volatile unsigned*)&g_rel < phase) { }
        }
        __syncthreads();
    }
}

// ---------------- horner: 7 steps with P32 + readout -------------------------
__global__ void __launch_bounds__(256, 1)
horner_kernel(const float* __restrict__ Wo, const float* __restrict__ bo,
              float* __restrict__ out) {
    extern __shared__ float Ps[];     // 8 x 512 = 16KB
    int tid = threadIdx.x, w = tid >> 5, lane = tid & 31;
    int cta = blockIdx.x;
    const float* P32 = g_P[4];
    for (int u = tid; u < 8 * 128; u += 256) {
        int rr = u >> 7, c = (u & 127) * 4;
        *(float4*)&Ps[rr * H + c] = *(const float4*)&P32[(size_t)(cta * 8 + rr) * H + c];
    }
    __syncthreads();

    for (int t = 0; t < 7; t++) {
        int i = cta * 8 + w;
        const float* src = (t == 0) ? &g_V5[7 * H] : g_w[(t - 1) & 1];
        float acc = 0.f;
#pragma unroll
        for (int jj = 0; jj < 4; jj++) {
            float4 pv = *(const float4*)&Ps[w * H + jj * 128 + lane * 4];
            float4 vv = __ldcg((const float4*)(src + jj * 128 + lane * 4));
            acc += pv.x*vv.x + pv.y*vv.y + pv.z*vv.z + pv.w*vv.w;
        }
#pragma unroll
        for (int s = 16; s > 0; s >>= 1) acc += __shfl_xor_sync(0xffffffffu, acc, s);
        if (lane == 0)
            g_w[t & 1][i] = acc + __ldcg(&g_V5[(size_t)(6 - t) * H + i]);
        gridbar((unsigned)(t + 1));
    }

    if (cta == 0) {
        __shared__ float sl[NOUT];
        float* hsm = Ps;
        if (tid < 128)
            *(float4*)&hsm[tid * 4] = __ldcg((const float4*)&g_w[0][tid * 4]);
        __syncthreads();
        if (w < NOUT) {
            const float* wr = Wo + (size_t)w * H;
            float acc = 0.f;
#pragma unroll
            for (int jj = 0; jj < 4; jj++) {
                float4 pv = *(const float4*)(wr + jj * 128 + lane * 4);
                float4 vv = *(const float4*)&hsm[jj * 128 + lane * 4];
                acc += pv.x*vv.x + pv.y*vv.y + pv.z*vv.z + pv.w*vv.w;
            }
#pragma unroll
            for (int s = 16; s > 0; s >>= 1) acc += __shfl_xor_sync(0xffffffffu, acc, s);
            if (lane == 0) sl[w] = acc + bo[w];
        }
        __syncthreads();
        if (tid == 0) {
            float mx = sl[0];
            for (int o = 1; o < NOUT; o++) mx = fmaxf(mx, sl[o]);
            float se = 0.f;
            for (int o = 0; o < NOUT; o++) se += expf(sl[o] - mx);
            float lse = mx + logf(se);
            for (int o = 0; o < NOUT; o++) out[o] = sl[o] - lse;
        }
    }
}

// ---------------- launch (R11 structure; record-before-wait) -----------------
extern "C" void kernel_launch(void* const* d_in, const int* in_sizes, int n_in,
                              void* d_out, int out_size) {
    const int*   tokens = (const int*)d_in[0];
    const float* emb    = (const float*)d_in[1];
    const float* Wi     = (const float*)d_in[2];
    const float* bi     = (const float*)d_in[3];
    const float* Wo     = (const float*)d_in[4];
    const float* bo     = (const float*)d_in[5];
    float* out = (float*)d_out;

    static cudaStream_t s1 = nullptr;
    static cudaEvent_t eRoot, eZ, eP[4], eL5;
    static float *pV1, *pV2, *pV3, *pV4, *pV5, *pP;
    if (!s1) {
        cudaStreamCreateWithFlags(&s1, cudaStreamNonBlocking);
        cudaEventCreateWithFlags(&eRoot, cudaEventDisableTiming);
        cudaEventCreateWithFlags(&eZ,    cudaEventDisableTiming);
        for (int i = 0; i < 4; i++) cudaEventCreateWithFlags(&eP[i], cudaEventDisableTiming);
        cudaEventCreateWithFlags(&eL5,   cudaEventDisableTiming);
        cudaGetSymbolAddress((void**)&pV1, g_V1);
        cudaGetSymbolAddress((void**)&pV2, g_V2);
        cudaGetSymbolAddress((void**)&pV3, g_V3);
        cudaGetSymbolAddress((void**)&pV4, g_V4);
        cudaGetSymbolAddress((void**)&pV5, g_V5);
        cudaGetSymbolAddress((void**)&pP,  g_P);
        cudaFuncSetAttribute(sqmm_mma, cudaFuncAttributeMaxDynamicSharedMemorySize, SQ_SMEM);
    }
    const float* Wh = Wi + IN_DIM;          // ld 768
    float* P2  = pP + 0 * H * H;
    float* P4  = pP + 1 * H * H;
    float* P8  = pP + 2 * H * H;
    float* P16 = pP + 3 * H * H;
    float* P32 = pP + 4 * H * H;

    // ---- fork ----
    cudaEventRecord(eRoot, 0);
    cudaStreamWaitEvent(s1, eRoot, 0);

    // ---- s1 prefix: zero P4..P32 + V2..V5 (record eZ), xfuse ----
    zeroRest_kernel<<<1096, 256, 0, s1>>>();
    cudaEventRecord(eZ, s1);
    xfuse_kernel<<<128, 256, 0, s1>>>(tokens, emb, Wi, bi);

    // ---- s0: critical path — zeroP2 then 5 tf32-MMA squarings ----
    zeroP2_kernel<<<256, 256>>>();
    sqmm_mma<<<dim3(8, 8, 4), 128, SQ_SMEM>>>(Wh,  768, P2);   cudaEventRecord(eP[0], 0);
    cudaStreamWaitEvent(0, eZ, 0);
    sqmm_mma<<<dim3(8, 8, 4), 128, SQ_SMEM>>>(P2,  512, P4);   cudaEventRecord(eP[1], 0);
    sqmm_mma<<<dim3(8, 8, 4), 128, SQ_SMEM>>>(P4,  512, P8);   cudaEventRecord(eP[2], 0);
    sqmm_mma<<<dim3(8, 8, 4), 128, SQ_SMEM>>>(P8,  512, P16);  cudaEventRecord(eP[3], 0);
    sqmm_mma<<<dim3(8, 8, 4), 128, SQ_SMEM>>>(P16, 512, P32);

    // ---- s1: tree levels L2..L5 (waits on already-recorded events) ----
    cudaStreamWaitEvent(s1, eP[0], 0);
    gemm_nt<<<dim3(4, 8, 2), 256, 0, s1>>>(pV1 + H, 2 * H, P2,  512, pV1, 2 * H, nullptr, pV2, H);
    cudaStreamWaitEvent(s1, eP[1], 0);
    gemm_nt<<<dim3(2, 8, 4), 256, 0, s1>>>(pV2 + H, 2 * H, P4,  512, pV2, 2 * H, nullptr, pV3, H);
    cudaStreamWaitEvent(s1, eP[2], 0);
    gemm_nt<<<dim3(1, 8, 8), 256, 0, s1>>>(pV3 + H, 2 * H, P8,  512, pV3, 2 * H, nullptr, pV4, H);
    cudaStreamWaitEvent(s1, eP[3], 0);
    gemm_nt<<<dim3(1, 8, 8), 256, 0, s1>>>(pV4 + H, 2 * H, P16, 512, pV4, 2 * H, nullptr, pV5, H);
    cudaEventRecord(eL5, s1);

    // ---- join: horner (needs P32 in-stream + eL5) ----
    cudaStreamWaitEvent(0, eL5, 0);
    horner_kernel<<<HC, 256, 8 * H * sizeof(float)>>>(Wo, bo, out);
}

// round 17
// speedup vs baseline: 1.4888x; 1.0329x over previous
#include <cuda_runtime.h>
#include <math.h>
#include <stdint.h>

#define H      512
#define IN_DIM 256
#define TSEQ   4096
#define NOUT   5
#define HC     32           // horner grid (32 CTAs x 8 warps, 16 rows/CTA)

// ---------------- static device scratch ------------------------------------
__device__ __align__(16) float g_V1[128 * H];   // level-1 (xfuse)
__device__ __align__(16) float g_V2[ 64 * H];
__device__ __align__(16) float g_V3[ 32 * H];
__device__ __align__(16) float g_V4[ 16 * H];   // 16 valid rows
__device__ __align__(16) float g_V5[  8 * H];   // 8 rows (horner inputs)
__device__ __align__(16) float g_P[5][H * H];   // Wh^2,4,8,16,32
__device__ __align__(16) float g_w[2][H];
__device__ unsigned g_arr[HC];
__device__ unsigned g_rel;

// ---------------- tf32 helpers ----------------------------------------------
__device__ __forceinline__ uint32_t tf32r(float x) {
    uint32_t y;
    asm("cvt.rna.tf32.f32 %0, %1;" : "=r"(y) : "f"(x));
    return y;
}
__device__ __forceinline__ void mma_tf32(float* c, const uint32_t* a, const uint32_t* b) {
    asm volatile("mma.sync.aligned.m16n8k8.row.col.f32.tf32.tf32.f32 "
        "{%0,%1,%2,%3}, {%4,%5,%6,%7}, {%8,%9}, {%0,%1,%2,%3};"
        : "+f"(c[0]), "+f"(c[1]), "+f"(c[2]), "+f"(c[3])
        : "r"(a[0]), "r"(a[1]), "r"(a[2]), "r"(a[3]), "r"(b[0]), "r"(b[1]));
}

// ---------------- zeroP2: P2 + barrier state ---------------------------------
__global__ void zeroP2_kernel() {
    int t = blockIdx.x * blockDim.x + threadIdx.x;   // 0..65535
    ((float4*)g_P)[t] = make_float4(0.f, 0.f, 0.f, 0.f);
    if (t < HC) g_arr[t] = 0u;
    if (t == 0) g_rel = 0u;
}

// ---------------- zeroRest: P4..P32 + V2..V4 ---------------------------------
__global__ void zeroRest_kernel() {
    int t = blockIdx.x * blockDim.x + threadIdx.x;
    float4 z = make_float4(0.f, 0.f, 0.f, 0.f);
    const int nP = 4 * H * H / 4;
    if (t < nP) { ((float4*)(g_P[1]))[t] = z; return; }
    int u = t - nP;
    if      (u <  8192) ((float4*)g_V2)[u] = z;
    else if (u < 12288) ((float4*)g_V3)[u - 8192] = z;
    else if (u < 14336) ((float4*)g_V4)[u - 12288] = z;
}

// ---------------- xfuse: gather + xproj + tree level 1 ----------------------
// CTA r (128): V1[r] = y_{2r} + Wh*y_{2r+1},  y_k = Wx*emb[tok[T-1-k]] + bi
__global__ void __launch_bounds__(256, 1)
xfuse_kernel(const int* __restrict__ tokens, const float* __restrict__ emb,
             const float* __restrict__ Wi, const float* __restrict__ bi) {
    __shared__ float xe[IN_DIM], xo[IN_DIM], ve[H], vo[H];
    __shared__ int stok[2];
    int tid = threadIdx.x, w = tid >> 5, lane = tid & 31;
    int r = blockIdx.x;
    if (tid < 2) stok[tid] = tokens[TSEQ - 1 - 2 * r - tid];
    __syncthreads();
    {
        const float* ee = emb + (size_t)stok[0] * IN_DIM;
        const float* eo = emb + (size_t)stok[1] * IN_DIM;
        xe[tid] = ee[tid];
        xo[tid] = eo[tid];
    }
    __syncthreads();
    for (int i = w; i < H; i += 8) {
        const float* wr = Wi + (size_t)i * 768 + lane * 8;
        float4 a0 = *(const float4*)wr;
        float4 a1 = *(const float4*)(wr + 4);
        float4 xe0 = *(const float4*)&xe[lane * 8];
        float4 xe1 = *(const float4*)&xe[lane * 8 + 4];
        float4 xo0 = *(const float4*)&xo[lane * 8];
        float4 xo1 = *(const float4*)&xo[lane * 8 + 4];
        float ae = a0.x*xe0.x + a0.y*xe0.y + a0.z*xe0.z + a0.w*xe0.w
                 + a1.x*xe1.x + a1.y*xe1.y + a1.z*xe1.z + a1.w*xe1.w;
        float ao = a0.x*xo0.x + a0.y*xo0.y + a0.z*xo0.z + a0.w*xo0.w
                 + a1.x*xo1.x + a1.y*xo1.y + a1.z*xo1.z + a1.w*xo1.w;
#pragma unroll
        for (int s = 16; s > 0; s >>= 1) {
            ae += __shfl_xor_sync(0xffffffffu, ae, s);
            ao += __shfl_xor_sync(0xffffffffu, ao, s);
        }
        if (lane == 0) {
            float b = bi[i];
            ve[i] = ae + b;
            vo[i] = ao + b;
        }
    }
    __syncthreads();
    for (int i = w; i < H; i += 8) {
        const float* hr = Wi + (size_t)i * 768 + IN_DIM;
        float acc = 0.f;
#pragma unroll
        for (int jj = 0; jj < 4; jj++) {
            float4 hv = *(const float4*)(hr + jj * 128 + lane * 4);
            float4 vv = *(const float4*)&vo[jj * 128 + lane * 4];
            acc += hv.x*vv.x + hv.y*vv.y + hv.z*vv.z + hv.w*vv.w;
        }
#pragma unroll
        for (int s = 16; s > 0; s >>= 1) acc += __shfl_xor_sync(0xffffffffu, acc, s);
        if (lane == 0) g_V1[(size_t)r * H + i] = acc + ve[i];
    }
}

// ---------------- generic NT GEMM (tree levels L2..L4) -----------------------
__global__ void gemm_nt(const float* __restrict__ A, int lda,
                        const float* __restrict__ B, int ldb,
                        const float* __restrict__ D, int ldd,
                        const float* __restrict__ bias,
                        float* __restrict__ C, int Ktot) {
    __shared__ float As[16][34];
    __shared__ float Bs[32][68];
    int tid = threadIdx.x;
    int r0 = blockIdx.x * 16;
    int j0 = blockIdx.y * 64;
    int nz = gridDim.z;
    int chunk = Ktot / nz;
    int kbeg = blockIdx.z * chunk;
    int r  = tid >> 4;
    int c4 = tid & 15;
    float acc[4] = {0.f, 0.f, 0.f, 0.f};
    for (int kt = kbeg; kt < kbeg + chunk; kt += 32) {
        {
            int row = tid >> 4, kp = (tid & 15) * 2;
            const float* p = A + (size_t)(r0 + row) * lda + kt + kp;
            float2 v = *(const float2*)p;
            As[row][kp] = v.x; As[row][kp + 1] = v.y;
        }
        {
            int row = tid >> 2, kp = (tid & 3) * 8;
            const float* p = B + (size_t)(j0 + row) * ldb + kt + kp;
            float4 v0 = *(const float4*)p;
            float4 v1 = *(const float4*)(p + 4);
            Bs[kp + 0][row] = v0.x; Bs[kp + 1][row] = v0.y;
            Bs[kp + 2][row] = v0.z; Bs[kp + 3][row] = v0.w;
            Bs[kp + 4][row] = v1.x; Bs[kp + 5][row] = v1.y;
            Bs[kp + 6][row] = v1.z; Bs[kp + 7][row] = v1.w;
        }
        __syncthreads();
#pragma unroll
        for (int k = 0; k < 32; k++) {
            float a = As[r][k];
            float4 b = *(const float4*)&Bs[k][c4 * 4];
            acc[0] += a * b.x; acc[1] += a * b.y;
            acc[2] += a * b.z; acc[3] += a * b.w;
        }
        __syncthreads();
    }
    int row = r0 + r;
    int col = j0 + c4 * 4;
    if (nz == 1) {
        float4 o;
        o.x = acc[0]; o.y = acc[1]; o.z = acc[2]; o.w = acc[3];
        if (D) {
            const float4 d = *(const float4*)&D[(size_t)row * ldd + col];
            o.x += d.x; o.y += d.y; o.z += d.z; o.w += d.w;
        }
        if (bias) {
            const float4 b = *(const float4*)&bias[col];
            o.x += b.x; o.y += b.y; o.z += b.z; o.w += b.w;
        }
        *(float4*)&C[(size_t)row * H + col] = o;
    } else {
        bool z0 = (blockIdx.z == 0);
#pragma unroll
        for (int t = 0; t < 4; t++) {
            float v = acc[t];
            if (z0 && D) v += D[(size_t)row * ldd + col + t];
            atomicAdd(&C[(size_t)row * H + col + t], v);
        }
    }
}

// ---------------- sqmm_mma: exact R11 version (measured 11.456us) ------------
// 128x64 tile, 256 threads (8 warps of 32x32), split-K=4 (chunk 128).
// grid (4,8,4) = 128 CTAs. C pre-zeroed (atomicAdd epilogue).
#define SQ_AH 0
#define SQ_AL 4608
#define SQ_BH 9216
#define SQ_BL 11392
#define SQ_SMEM (13568 * 4)

__global__ void __launch_bounds__(256, 1)
sqmm_mma(const float* __restrict__ A, int lda, float* __restrict__ C) {
    extern __shared__ float sm[];
    float* AH = sm + SQ_AH;
    float* AL = sm + SQ_AL;
    float* BH = sm + SQ_BH;
    float* BL = sm + SQ_BL;
    int tid = threadIdx.x, wid = tid >> 5, lane = tid & 31;
    int g = lane >> 2, t = lane & 3;
    int m0 = blockIdx.x * 128;
    int n0 = blockIdx.y * 64;
    int kbeg = blockIdx.z * 128;
    int wr = (wid >> 1) * 32;
    int wc = (wid & 1) * 32;

    float c_[2][4][4];
#pragma unroll
    for (int mt = 0; mt < 2; mt++)
#pragma unroll
        for (int nt = 0; nt < 4; nt++)
#pragma unroll
            for (int q = 0; q < 4; q++) c_[mt][nt][q] = 0.f;

#pragma unroll
    for (int kt = 0; kt < 4; kt++) {
        int kb = kbeg + kt * 32;
#pragma unroll
        for (int u0 = 0; u0 < 4; u0++) {
            int u = u0 * 256 + tid;
            int row = u >> 3, col = (u & 7) * 4;
            float4 v = *(const float4*)&A[(size_t)(m0 + row) * lda + kb + col];
            uint32_t h0 = tf32r(v.x), h1 = tf32r(v.y), h2 = tf32r(v.z), h3 = tf32r(v.w);
            uint4 hv; hv.x = h0; hv.y = h1; hv.z = h2; hv.w = h3;
            uint4 lv;
            lv.x = tf32r(v.x - __uint_as_float(h0));
            lv.y = tf32r(v.y - __uint_as_float(h1));
            lv.z = tf32r(v.z - __uint_as_float(h2));
            lv.w = tf32r(v.w - __uint_as_float(h3));
            *(uint4*)&AH[row * 36 + col] = hv;
            *(uint4*)&AL[row * 36 + col] = lv;
        }
#pragma unroll
        for (int u0 = 0; u0 < 2; u0++) {
            int u = u0 * 256 + tid;
            int row = u >> 4, col = (u & 15) * 4;
            float4 v = *(const float4*)&A[(size_t)(kb + row) * lda + n0 + col];
            uint32_t h0 = tf32r(v.x), h1 = tf32r(v.y), h2 = tf32r(v.z), h3 = tf32r(v.w);
            uint4 hv; hv.x = h0; hv.y = h1; hv.z = h2; hv.w = h3;
            uint4 lv;
            lv.x = tf32r(v.x - __uint_as_float(h0));
            lv.y = tf32r(v.y - __uint_as_float(h1));
            lv.z = tf32r(v.z - __uint_as_float(h2));
            lv.w = tf32r(v.w - __uint_as_float(h3));
            *(uint4*)&BH[row * 68 + col] = hv;
            *(uint4*)&BL[row * 68 + col] = lv;
        }
        __syncthreads();
#pragma unroll
        for (int kk = 0; kk < 32; kk += 8) {
            uint32_t ah[2][4], al[2][4], bh[4][2], bl[4][2];
#pragma unroll
            for (int mt = 0; mt < 2; mt++) {
                int r = wr + mt * 16 + g;
                const float* ph = &AH[r * 36 + kk + t];
                const float* pl = &AL[r * 36 + kk + t];
                ah[mt][0] = __float_as_uint(ph[0]);
                ah[mt][1] = __float_as_uint(ph[8 * 36]);
                ah[mt][2] = __float_as_uint(ph[4]);
                ah[mt][3] = __float_as_uint(ph[8 * 36 + 4]);
                al[mt][0] = __float_as_uint(pl[0]);
                al[mt][1] = __float_as_uint(pl[8 * 36]);
                al[mt][2] = __float_as_uint(pl[4]);
                al[mt][3] = __float_as_uint(pl[8 * 36 + 4]);
            }
#pragma unroll
            for (int nt = 0; nt < 4; nt++) {
                int cc = wc + nt * 8 + g;
                bh[nt][0] = __float_as_uint(BH[(kk + t) * 68 + cc]);
                bh[nt][1] = __float_as_uint(BH[(kk + t + 4) * 68 + cc]);
                bl[nt][0] = __float_as_uint(BL[(kk + t) * 68 + cc]);
                bl[nt][1] = __float_as_uint(BL[(kk + t + 4) * 68 + cc]);
            }
#pragma unroll
            for (int mt = 0; mt < 2; mt++)
#pragma unroll
                for (int nt = 0; nt < 4; nt++) {
                    mma_tf32(c_[mt][nt], ah[mt], bh[nt]);
                    mma_tf32(c_[mt][nt], ah[mt], bl[nt]);
                    mma_tf32(c_[mt][nt], al[mt], bh[nt]);
                }
        }
        __syncthreads();
    }
#pragma unroll
    for (int mt = 0; mt < 2; mt++)
#pragma unroll
        for (int nt = 0; nt < 4; nt++) {
            int r = m0 + wr + mt * 16 + g;
            int cc = n0 + wc + nt * 8 + t * 2;
            atomicAdd(&C[(size_t)r * H + cc],           c_[mt][nt][0]);
            atomicAdd(&C[(size_t)r * H + cc + 1],       c_[mt][nt][1]);
            atomicAdd(&C[(size_t)(r + 8) * H + cc],     c_[mt][nt][2]);
            atomicAdd(&C[(size_t)(r + 8) * H + cc + 1], c_[mt][nt][3]);
        }
}

// ---------------- grid barrier (HC=32 CTAs, per-CTA flags) -------------------
__device__ __forceinline__ void gridbar(unsigned phase) {
    __threadfence();
    __syncthreads();
    int tid = threadIdx.x;
    if (blockIdx.x == 0) {
        if (tid > 0 && tid < HC) {
            while (*(volatile unsigned*)&g_arr[tid] < phase) { }
        }
        __syncthreads();
        if (tid == 0) {
            __threadfence();
            *(volatile unsigned*)&g_rel = phase;
        }
        __syncthreads();
    } else {
        if (tid == 0) {
            *(volatile unsigned*)&g_arr[blockIdx.x] = phase;
            while (*(volatile unsigned*)&g_rel < phase) { }
        }
        __syncthreads();
    }
}

// ---------------- horner: L5 prologue + 7 steps (P32) + readout --------------
// MUST launch with HC=32 CTAs x 256 threads, 32KB dynamic smem.
// CTA owns rows [cta*16, cta*16+16); warp w owns rows cta*16 + 2w + {0,1}.
__global__ void __launch_bounds__(256, 1)
horner_kernel(const float* __restrict__ Wo, const float* __restrict__ bo,
              float* __restrict__ out) {
    extern __shared__ float sm[];     // 8192 floats (32KB)
    int tid = threadIdx.x, w = tid >> 5, lane = tid & 31;
    int cta = blockIdx.x;
    const float* P16 = g_P[3];
    const float* P32 = g_P[4];

    // ---- prologue (L5): V5[p] = V4[2p] + P16*V4[2p+1], rows owned by CTA ----
    float* Vodd = sm;                 // 8 x 512 = 16KB
    for (int u = tid; u < 8 * 128; u += 256) {
        int pp = u >> 7, c = (u & 127) * 4;
        *(float4*)&Vodd[pp * H + c] = *(const float4*)&g_V4[(size_t)(2 * pp + 1) * H + c];
    }
    __syncthreads();
#pragma unroll
    for (int rr = 0; rr < 2; rr++) {
        int i = cta * 16 + w * 2 + rr;
        const float* prow = P16 + (size_t)i * H;
        float4 pv[4];
#pragma unroll
        for (int jj = 0; jj < 4; jj++)
            pv[jj] = *(const float4*)(prow + jj * 128 + lane * 4);
        for (int p = 0; p < 8; p++) {
            float acc = 0.f;
#pragma unroll
            for (int jj = 0; jj < 4; jj++) {
                float4 vv = *(const float4*)&Vodd[p * H + jj * 128 + lane * 4];
                acc += pv[0].x * 0.f + pv[jj].x * vv.x + pv[jj].y * vv.y
                     + pv[jj].z * vv.z + pv[jj].w * vv.w;
            }
#pragma unroll
            for (int s = 16; s > 0; s >>= 1) acc += __shfl_xor_sync(0xffffffffu, acc, s);
            if (lane == 0)
                g_V5[(size_t)p * H + i] = acc + g_V4[(size_t)(2 * p) * H + i];
        }
    }
    gridbar(1);

    // ---- cache this CTA's 16 P32 rows (32KB; overwrites Vodd) ----
    __syncthreads();
    for (int u = tid; u < 16 * 128; u += 256) {
        int rr = u >> 7, c = (u & 127) * 4;
        *(float4*)&sm[rr * H + c] = *(const float4*)&P32[(size_t)(cta * 16 + rr) * H + c];
    }
    __syncthreads();

    // ---- Horner: w=u7; t=0..6: w = P32*w + u[6-t] ----
    for (int t = 0; t < 7; t++) {
        const float* src = (t == 0) ? &g_V5[7 * H] : g_w[(t - 1) & 1];
        float4 vv[4];
#pragma unroll
        for (int jj = 0; jj < 4; jj++)
            vv[jj] = __ldcg((const float4*)(src + jj * 128 + lane * 4));
#pragma unroll
        for (int rr = 0; rr < 2; rr++) {
            int rw = w * 2 + rr;
            int i = cta * 16 + rw;
            float acc = 0.f;
#pragma unroll
            for (int jj = 0; jj < 4; jj++) {
                float4 pv = *(const float4*)&sm[rw * H + jj * 128 + lane * 4];
                acc += pv.x*vv[jj].x + pv.y*vv[jj].y + pv.z*vv[jj].z + pv.w*vv[jj].w;
            }
#pragma unroll
            for (int s = 16; s > 0; s >>= 1) acc += __shfl_xor_sync(0xffffffffu, acc, s);
            if (lane == 0)
                g_w[t & 1][i] = acc + __ldcg(&g_V5[(size_t)(6 - t) * H + i]);
        }
        gridbar((unsigned)(t + 2));
    }

    // ---- readout (CTA 0): h in g_w[0] (t=6) ----
    if (cta == 0) {
        __shared__ float sl[NOUT];
        float* hsm = sm;              // reuse
        if (tid < 128)
            *(float4*)&hsm[tid * 4] = __ldcg((const float4*)&g_w[0][tid * 4]);
        __syncthreads();
        if (w < NOUT) {
            const float* wr = Wo + (size_t)w * H;
            float acc = 0.f;
#pragma unroll
            for (int jj = 0; jj < 4; jj++) {
                float4 pv = *(const float4*)(wr + jj * 128 + lane * 4);
                float4 vv = *(const float4*)&hsm[jj * 128 + lane * 4];
                acc += pv.x*vv.x + pv.y*vv.y + pv.z*vv.z + pv.w*vv.w;
            }
#pragma unroll
            for (int s = 16; s > 0; s >>= 1) acc += __shfl_xor_sync(0xffffffffu, acc, s);
            if (lane == 0) sl[w] = acc + bo[w];
        }
        __syncthreads();
        if (tid == 0) {
            float mx = sl[0];
            for (int o = 1; o < NOUT; o++) mx = fmaxf(mx, sl[o]);
            float se = 0.f;
            for (int o = 0; o < NOUT; o++) se += expf(sl[o] - mx);
            float lse = mx + logf(se);
            for (int o = 0; o < NOUT; o++) out[o] = sl[o] - lse;
        }
    }
}

// ---------------- launch (record-before-wait in enqueue order) ---------------
extern "C" void kernel_launch(void* const* d_in, const int* in_sizes, int n_in,
                              void* d_out, int out_size) {
    const int*   tokens = (const int*)d_in[0];
    const float* emb    = (const float*)d_in[1];
    const float* Wi     = (const float*)d_in[2];
    const float* bi     = (const float*)d_in[3];
    const float* Wo     = (const float*)d_in[4];
    const float* bo     = (const float*)d_in[5];
    float* out = (float*)d_out;

    static cudaStream_t s1 = nullptr;
    static cudaEvent_t eRoot, eZ, eP[3], eL4;
    static float *pV1, *pV2, *pV3, *pV4, *pP;
    if (!s1) {
        cudaStreamCreateWithFlags(&s1, cudaStreamNonBlocking);
        cudaEventCreateWithFlags(&eRoot, cudaEventDisableTiming);
        cudaEventCreateWithFlags(&eZ,    cudaEventDisableTiming);
        for (int i = 0; i < 3; i++) cudaEventCreateWithFlags(&eP[i], cudaEventDisableTiming);
        cudaEventCreateWithFlags(&eL4,   cudaEventDisableTiming);
        cudaGetSymbolAddress((void**)&pV1, g_V1);
        cudaGetSymbolAddress((void**)&pV2, g_V2);
        cudaGetSymbolAddress((void**)&pV3, g_V3);
        cudaGetSymbolAddress((void**)&pV4, g_V4);
        cudaGetSymbolAddress((void**)&pP,  g_P);
        cudaFuncSetAttribute(sqmm_mma, cudaFuncAttributeMaxDynamicSharedMemorySize, SQ_SMEM);
        cudaFuncSetAttribute(horner_kernel, cudaFuncAttributeMaxDynamicSharedMemorySize, 32768);
    }
    const float* Wh = Wi + IN_DIM;          // ld 768
    float* P2  = pP + 0 * H * H;
    float* P4  = pP + 1 * H * H;
    float* P8  = pP + 2 * H * H;
    float* P16 = pP + 3 * H * H;
    float* P32 = pP + 4 * H * H;

    // ---- fork ----
    cudaEventRecord(eRoot, 0);
    cudaStreamWaitEvent(s1, eRoot, 0);

    // ---- s1 prefix: zero P4..P32 + V2..V4 (record eZ), xfuse ----
    zeroRest_kernel<<<1080, 256, 0, s1>>>();
    cudaEventRecord(eZ, s1);
    xfuse_kernel<<<128, 256, 0, s1>>>(tokens, emb, Wi, bi);

    // ---- s0: critical path — zeroP2 then 5 tf32-MMA squarings ----
    zeroP2_kernel<<<256, 256>>>();
    sqmm_mma<<<dim3(4, 8, 4), 256, SQ_SMEM>>>(Wh,  768, P2);   cudaEventRecord(eP[0], 0);
    cudaStreamWaitEvent(0, eZ, 0);
    sqmm_mma<<<dim3(4, 8, 4), 256, SQ_SMEM>>>(P2,  512, P4);   cudaEventRecord(eP[1], 0);
    sqmm_mma<<<dim3(4, 8, 4), 256, SQ_SMEM>>>(P4,  512, P8);   cudaEventRecord(eP[2], 0);
    sqmm_mma<<<dim3(4, 8, 4), 256, SQ_SMEM>>>(P8,  512, P16);
    sqmm_mma<<<dim3(4, 8, 4), 256, SQ_SMEM>>>(P16, 512, P32);

    // ---- s1: tree levels L2..L4 (waits on already-recorded events) ----
    cudaStreamWaitEvent(s1, eP[0], 0);
    gemm_nt<<<dim3(4, 8, 2), 256, 0, s1>>>(pV1 + H, 2 * H, P2, 512, pV1, 2 * H, nullptr, pV2, H);
    cudaStreamWaitEvent(s1, eP[1], 0);
    gemm_nt<<<dim3(2, 8, 4), 256, 0, s1>>>(pV2 + H, 2 * H, P4, 512, pV2, 2 * H, nullptr, pV3, H);
    cudaStreamWaitEvent(s1, eP[2], 0);
    gemm_nt<<<dim3(1, 8, 8), 256, 0, s1>>>(pV3 + H, 2 * H, P8, 512, pV3, 2 * H, nullptr, pV4, H);
    cudaEventRecord(eL4, s1);

    // ---- join: horner (needs P16,P32 in-stream + V4 via eL4) ----
    cudaStreamWaitEvent(0, eL4, 0);
    horner_kernel<<<HC, 256, 32768>>>(Wo, bo, out);
}